// round 3
// baseline (speedup 1.0000x reference)
#include <cuda_runtime.h>
#include <math.h>

#define NN 50000
#define NE 800000
#define F  128

// ---------------- scratch (device globals; no allocation allowed) ----------
__device__ __align__(16) float g_feat[NN * F];
__device__ __align__(16) float g_h1[NN * F];
__device__ __align__(16) float g_h2[NN * F];
__device__ __align__(16) float g_el[NN * 4];
__device__ __align__(16) float g_er[NN * 4];
__device__ int g_rowptr[NN + 1];

// ---------------- row_ptr from sorted dst via lower_bound ------------------
__global__ void rowptr_kernel(const int* __restrict__ dst) {
    int n = blockIdx.x * blockDim.x + threadIdx.x;
    if (n > NN) return;
    int lo = 0, hi = NE;
    while (lo < hi) {
        int mid = (lo + hi) >> 1;
        if (dst[mid] < n) lo = mid + 1; else hi = mid;
    }
    g_rowptr[n] = lo;
}

// ---------------- fused GEMM (feat = h @ W) + el/er projections ------------
// Block: 128 threads (thread j = output column j), 32 rows per block.
// el[n][h] = sum_d feat[n,h,d]*al[h,d]; warp w covers columns 32w..32w+31 =
// exactly head w, so a warp-sum of feat[n][j]*al[j] gives el[n][w].
__global__ __launch_bounds__(128) void gemm_attn_kernel(
    const float* __restrict__ hin, const float* __restrict__ W,
    const float* __restrict__ al, const float* __restrict__ ar)
{
    __shared__ float hs[32][F];
    const int j = threadIdx.x;
    const int base = blockIdx.x * 32;

    #pragma unroll
    for (int r = 0; r < 32; r++) {
        int n = base + r;
        hs[r][j] = (n < NN) ? hin[n * F + j] : 0.f;
    }
    __syncthreads();

    float acc[32];
    #pragma unroll
    for (int r = 0; r < 32; r++) acc[r] = 0.f;

    for (int k4 = 0; k4 < F / 4; k4++) {
        float w0 = __ldg(&W[(4 * k4 + 0) * F + j]);
        float w1 = __ldg(&W[(4 * k4 + 1) * F + j]);
        float w2 = __ldg(&W[(4 * k4 + 2) * F + j]);
        float w3 = __ldg(&W[(4 * k4 + 3) * F + j]);
        #pragma unroll
        for (int r = 0; r < 32; r++) {
            float4 h4 = *reinterpret_cast<const float4*>(&hs[r][4 * k4]);
            acc[r] = fmaf(h4.x, w0, fmaf(h4.y, w1, fmaf(h4.z, w2, fmaf(h4.w, w3, acc[r]))));
        }
    }

    const float alj = __ldg(&al[j]);
    const float arj = __ldg(&ar[j]);
    const int lane = j & 31;
    const int warp = j >> 5;

    #pragma unroll
    for (int r = 0; r < 32; r++) {
        int n = base + r;
        float v = acc[r];
        float sl = v * alj;
        float sr = v * arj;
        #pragma unroll
        for (int off = 16; off > 0; off >>= 1) {
            sl += __shfl_xor_sync(0xffffffffu, sl, off);
            sr += __shfl_xor_sync(0xffffffffu, sr, off);
        }
        if (n < NN) {
            g_feat[n * F + j] = v;
            if (lane == 0) {
                g_el[n * 4 + warp] = sl;
                g_er[n * 4 + warp] = sr;
            }
        }
    }
}

// ---------------- per-dst-node edge softmax + weighted aggregation ---------
// One warp per dst node. Lane owns features [4*lane, 4*lane+4) (float4), all
// in head = lane>>3, so the attention weight is uniform per 8-lane group.
// Two passes over the node's contiguous (sorted-dst) edge range.
__global__ __launch_bounds__(256) void gat_agg_kernel(
    const int* __restrict__ src,
    const float* __restrict__ hres,   // residual input (may be null)
    float* __restrict__ out,
    int do_act, int do_mean)
{
    const int gw = (blockIdx.x * blockDim.x + threadIdx.x) >> 5;
    if (gw >= NN) return;
    const int lane = threadIdx.x & 31;
    const int n = gw;
    const int e0 = g_rowptr[n];
    const int e1 = g_rowptr[n + 1];
    const int head = lane >> 3;
    const float ern = g_er[n * 4 + head];

    // pass 1: per-head max (redundantly computed per 8-lane group; no reduce needed)
    float m = -1e30f;
    #pragma unroll 4
    for (int i = e0; i < e1; i++) {
        int s = __ldg(&src[i]);
        float e = __ldg(&g_el[s * 4 + head]) + ern;
        e = (e > 0.f) ? e : 0.2f * e;          // leaky_relu(0.2)
        m = fmaxf(m, e);
    }

    // pass 2: exp / sum / weighted gather-accumulate
    float ssum = 0.f;
    float4 acc = make_float4(0.f, 0.f, 0.f, 0.f);
    const float4* feat4 = reinterpret_cast<const float4*>(g_feat);
    #pragma unroll 4
    for (int i = e0; i < e1; i++) {
        int s = __ldg(&src[i]);
        float e = __ldg(&g_el[s * 4 + head]) + ern;
        e = (e > 0.f) ? e : 0.2f * e;
        float w = __expf(e - m);
        ssum += w;
        float4 f = __ldg(&feat4[s * 32 + lane]);
        acc.x = fmaf(w, f.x, acc.x);
        acc.y = fmaf(w, f.y, acc.y);
        acc.z = fmaf(w, f.z, acc.z);
        acc.w = fmaf(w, f.w, acc.w);
    }

    float inv = (e1 > e0) ? (1.f / ssum) : 0.f;   // empty segment -> 0 (matches ref)
    float4 o = make_float4(acc.x * inv, acc.y * inv, acc.z * inv, acc.w * inv);

    if (hres) {
        float4 r = __ldg(&reinterpret_cast<const float4*>(hres)[n * 32 + lane]);
        o.x += r.x; o.y += r.y; o.z += r.z; o.w += r.w;
    }
    if (do_act) {  // ELU(alpha=1)
        o.x = (o.x > 0.f) ? o.x : expm1f(o.x);
        o.y = (o.y > 0.f) ? o.y : expm1f(o.y);
        o.z = (o.z > 0.f) ? o.z : expm1f(o.z);
        o.w = (o.w > 0.f) ? o.w : expm1f(o.w);
    }

    if (do_mean) {
        // sum over 4 heads: fold lanes across xor 8 and xor 16
        o.x += __shfl_xor_sync(0xffffffffu, o.x, 8);
        o.y += __shfl_xor_sync(0xffffffffu, o.y, 8);
        o.z += __shfl_xor_sync(0xffffffffu, o.z, 8);
        o.w += __shfl_xor_sync(0xffffffffu, o.w, 8);
        o.x += __shfl_xor_sync(0xffffffffu, o.x, 16);
        o.y += __shfl_xor_sync(0xffffffffu, o.y, 16);
        o.z += __shfl_xor_sync(0xffffffffu, o.z, 16);
        o.w += __shfl_xor_sync(0xffffffffu, o.w, 16);
        if (lane < 8) {
            reinterpret_cast<float4*>(out)[n * 8 + lane] =
                make_float4(o.x * 0.25f, o.y * 0.25f, o.z * 0.25f, o.w * 0.25f);
        }
    } else {
        reinterpret_cast<float4*>(out)[n * 32 + lane] = o;
    }
}

// ---------------- launcher --------------------------------------------------
extern "C" void kernel_launch(void* const* d_in, const int* in_sizes, int n_in,
                              void* d_out, int out_size)
{
    const float* x   = (const float*)d_in[0];
    const int*   src = (const int*)d_in[1];
    const int*   dst = (const int*)d_in[2];
    const float* W0  = (const float*)d_in[3];
    const float* al0 = (const float*)d_in[4];
    const float* ar0 = (const float*)d_in[5];
    const float* W1  = (const float*)d_in[6];
    const float* al1 = (const float*)d_in[7];
    const float* ar1 = (const float*)d_in[8];
    const float* W2  = (const float*)d_in[9];
    const float* al2 = (const float*)d_in[10];
    const float* ar2 = (const float*)d_in[11];
    float* out = (float*)d_out;

    float *h1 = nullptr, *h2 = nullptr;
    cudaGetSymbolAddress((void**)&h1, g_h1);
    cudaGetSymbolAddress((void**)&h2, g_h2);

    const int gemm_grid = (NN + 31) / 32;     // 1563
    const int agg_grid  = (NN * 32) / 256;    // 6250 (exact)

    rowptr_kernel<<<(NN + 1 + 255) / 256, 256>>>(dst);

    // layer 0: no residual, ELU
    gemm_attn_kernel<<<gemm_grid, 128>>>(x, W0, al0, ar0);
    gat_agg_kernel<<<agg_grid, 256>>>(src, nullptr, h1, /*act=*/1, /*mean=*/0);

    // layer 1: residual (input h1), ELU
    gemm_attn_kernel<<<gemm_grid, 128>>>(h1, W1, al1, ar1);
    gat_agg_kernel<<<agg_grid, 256>>>(src, h1, h2, /*act=*/1, /*mean=*/0);

    // layer 2: residual (input h2), no act, mean over heads -> [N, 32]
    gemm_attn_kernel<<<gemm_grid, 128>>>(h2, W2, al2, ar2);
    gat_agg_kernel<<<agg_grid, 256>>>(src, h2, out, /*act=*/0, /*mean=*/1);
}

// round 4
// speedup vs baseline: 1.2316x; 1.2316x over previous
#include <cuda_runtime.h>
#include <math.h>

#define NN 50000
#define NE 800000
#define F  128
#define RPB 64            // rows per block in GEMM
#define HT_STRIDE 66      // padded row-length of transposed h tile (even, !=0 mod trick)

// ---------------- scratch (device globals; no allocation allowed) ----------
__device__ __align__(16) float g_feat[NN * F];
__device__ __align__(16) float g_h1[NN * F];
__device__ __align__(16) float g_h2[NN * F];
__device__ __align__(16) float g_el[NN * 4];
__device__ __align__(16) float g_er[NN * 4];
__device__ int g_rowptr[NN + 1];

// ---------------- f32x2 packed-math helpers (sm_10x dual fp32 pipe) --------
__device__ __forceinline__ unsigned long long pack2(float lo, float hi) {
    unsigned long long r;
    asm("mov.b64 %0, {%1, %2};" : "=l"(r) : "f"(lo), "f"(hi));
    return r;
}
__device__ __forceinline__ void unpack2(unsigned long long v, float& lo, float& hi) {
    asm("mov.b64 {%0, %1}, %2;" : "=f"(lo), "=f"(hi) : "l"(v));
}
__device__ __forceinline__ unsigned long long fma2(
    unsigned long long a, unsigned long long b, unsigned long long c) {
    unsigned long long d;
    asm("fma.rn.f32x2 %0, %1, %2, %3;" : "=l"(d) : "l"(a), "l"(b), "l"(c));
    return d;
}

// ---------------- row_ptr from sorted dst via lower_bound ------------------
__global__ void rowptr_kernel(const int* __restrict__ dst) {
    int n = blockIdx.x * blockDim.x + threadIdx.x;
    if (n > NN) return;
    int lo = 0, hi = NE;
    while (lo < hi) {
        int mid = (lo + hi) >> 1;
        if (dst[mid] < n) lo = mid + 1; else hi = mid;
    }
    g_rowptr[n] = lo;
}

// ---------------- register-tiled GEMM (feat = h @ W) + el/er projections ---
// 64 rows x 128 cols per block, 256 threads. Warp w owns local rows 8w..8w+7;
// lane cg owns cols 4cg..4cg+3 (all within head cg>>3). Row-pairs packed into
// f32x2 accumulators; h tile stored transposed so row-pairs load as one LDS.64
// broadcast. Whole W (64KB) cached in shared.
extern __shared__ float s_dyn[];

__global__ __launch_bounds__(256, 2) void gemm_attn_kernel(
    const float* __restrict__ hin, const float* __restrict__ W,
    const float* __restrict__ al, const float* __restrict__ ar)
{
    float* Wsh = s_dyn;                 // [128][128]
    float* hsT = s_dyn + F * F;         // [128][HT_STRIDE] (transposed h tile)
    const int tid  = threadIdx.x;
    const int base = blockIdx.x * RPB;

    // ---- load W (16384 floats, coalesced float4) ----
    {
        const float4* Wg  = reinterpret_cast<const float4*>(W);
        float4*       Ws4 = reinterpret_cast<float4*>(Wsh);
        #pragma unroll
        for (int i = 0; i < 16; i++) Ws4[tid + 256 * i] = Wg[tid + 256 * i];
    }
    // ---- load h tile, store transposed ----
    {
        const int k4 = tid & 31, r0 = tid >> 5;
        #pragma unroll
        for (int j = 0; j < 8; j++) {
            int r = r0 + 8 * j;
            int n = base + r;
            float4 v = (n < NN)
                ? *reinterpret_cast<const float4*>(&hin[n * F + 4 * k4])
                : make_float4(0.f, 0.f, 0.f, 0.f);
            hsT[(4 * k4 + 0) * HT_STRIDE + r] = v.x;
            hsT[(4 * k4 + 1) * HT_STRIDE + r] = v.y;
            hsT[(4 * k4 + 2) * HT_STRIDE + r] = v.z;
            hsT[(4 * k4 + 3) * HT_STRIDE + r] = v.w;
        }
    }
    __syncthreads();

    const int cg = tid & 31;        // column group: cols 4cg..4cg+3
    const int w  = tid >> 5;        // warp: local rows 8w..8w+7
    const int hb = 8 * w;

    unsigned long long acc[4][4];   // [row-pair][col]
    #pragma unroll
    for (int rp = 0; rp < 4; rp++)
        #pragma unroll
        for (int c = 0; c < 4; c++) acc[rp][c] = 0ull;

    #pragma unroll 4
    for (int k = 0; k < F; k++) {
        float4 wv = *reinterpret_cast<const float4*>(&Wsh[k * F + 4 * cg]);
        unsigned long long wp0 = pack2(wv.x, wv.x);
        unsigned long long wp1 = pack2(wv.y, wv.y);
        unsigned long long wp2 = pack2(wv.z, wv.z);
        unsigned long long wp3 = pack2(wv.w, wv.w);
        const unsigned long long* hp =
            reinterpret_cast<const unsigned long long*>(&hsT[k * HT_STRIDE + hb]);
        #pragma unroll
        for (int rp = 0; rp < 4; rp++) {
            unsigned long long h2 = hp[rp];   // rows (hb+2rp, hb+2rp+1) packed
            acc[rp][0] = fma2(h2, wp0, acc[rp][0]);
            acc[rp][1] = fma2(h2, wp1, acc[rp][1]);
            acc[rp][2] = fma2(h2, wp2, acc[rp][2]);
            acc[rp][3] = fma2(h2, wp3, acc[rp][3]);
        }
    }

    // ---- epilogue: store feat, compute per-head el/er ----
    const float4 alv = *reinterpret_cast<const float4*>(&al[4 * cg]);
    const float4 arv = *reinterpret_cast<const float4*>(&ar[4 * cg]);
    const int head = cg >> 3;

    #pragma unroll
    for (int rp = 0; rp < 4; rp++) {
        float a0[2], a1[2], a2[2], a3[2];
        unpack2(acc[rp][0], a0[0], a0[1]);
        unpack2(acc[rp][1], a1[0], a1[1]);
        unpack2(acc[rp][2], a2[0], a2[1]);
        unpack2(acc[rp][3], a3[0], a3[1]);
        #pragma unroll
        for (int rr = 0; rr < 2; rr++) {
            float sl = fmaf(a0[rr], alv.x, fmaf(a1[rr], alv.y,
                       fmaf(a2[rr], alv.z, a3[rr] * alv.w)));
            float sr = fmaf(a0[rr], arv.x, fmaf(a1[rr], arv.y,
                       fmaf(a2[rr], arv.z, a3[rr] * arv.w)));
            #pragma unroll
            for (int off = 1; off < 8; off <<= 1) {
                sl += __shfl_xor_sync(0xffffffffu, sl, off);
                sr += __shfl_xor_sync(0xffffffffu, sr, off);
            }
            int n = base + hb + 2 * rp + rr;
            if (n < NN) {
                *reinterpret_cast<float4*>(&g_feat[n * F + 4 * cg]) =
                    make_float4(a0[rr], a1[rr], a2[rr], a3[rr]);
                if ((cg & 7) == 0) {
                    g_el[n * 4 + head] = sl;
                    g_er[n * 4 + head] = sr;
                }
            }
        }
    }
}

// ---------------- per-dst-node edge softmax + weighted aggregation ---------
__global__ __launch_bounds__(256) void gat_agg_kernel(
    const int* __restrict__ src,
    const float* __restrict__ hres,   // residual input (may be null)
    float* __restrict__ out,
    int do_act, int do_mean)
{
    const int gw = (blockIdx.x * blockDim.x + threadIdx.x) >> 5;
    if (gw >= NN) return;
    const int lane = threadIdx.x & 31;
    const int n = gw;
    const int e0 = g_rowptr[n];
    const int e1 = g_rowptr[n + 1];
    const int head = lane >> 3;
    const float ern = g_er[n * 4 + head];

    // pass 1: per-head max (redundant per 8-lane group; no reduce needed)
    float m = -1e30f;
    #pragma unroll 4
    for (int i = e0; i < e1; i++) {
        int s = __ldg(&src[i]);
        float e = __ldg(&g_el[s * 4 + head]) + ern;
        e = (e > 0.f) ? e : 0.2f * e;          // leaky_relu(0.2)
        m = fmaxf(m, e);
    }

    // pass 2: exp / sum / weighted gather-accumulate
    float ssum = 0.f;
    float4 acc = make_float4(0.f, 0.f, 0.f, 0.f);
    const float4* feat4 = reinterpret_cast<const float4*>(g_feat);
    #pragma unroll 4
    for (int i = e0; i < e1; i++) {
        int s = __ldg(&src[i]);
        float e = __ldg(&g_el[s * 4 + head]) + ern;
        e = (e > 0.f) ? e : 0.2f * e;
        float wgt = __expf(e - m);
        ssum += wgt;
        float4 f = __ldg(&feat4[s * 32 + lane]);
        acc.x = fmaf(wgt, f.x, acc.x);
        acc.y = fmaf(wgt, f.y, acc.y);
        acc.z = fmaf(wgt, f.z, acc.z);
        acc.w = fmaf(wgt, f.w, acc.w);
    }

    float inv = (e1 > e0) ? (1.f / ssum) : 0.f;
    float4 o = make_float4(acc.x * inv, acc.y * inv, acc.z * inv, acc.w * inv);

    if (hres) {
        float4 r = __ldg(&reinterpret_cast<const float4*>(hres)[n * 32 + lane]);
        o.x += r.x; o.y += r.y; o.z += r.z; o.w += r.w;
    }
    if (do_act) {  // ELU(alpha=1)
        o.x = (o.x > 0.f) ? o.x : expm1f(o.x);
        o.y = (o.y > 0.f) ? o.y : expm1f(o.y);
        o.z = (o.z > 0.f) ? o.z : expm1f(o.z);
        o.w = (o.w > 0.f) ? o.w : expm1f(o.w);
    }

    if (do_mean) {
        o.x += __shfl_xor_sync(0xffffffffu, o.x, 8);
        o.y += __shfl_xor_sync(0xffffffffu, o.y, 8);
        o.z += __shfl_xor_sync(0xffffffffu, o.z, 8);
        o.w += __shfl_xor_sync(0xffffffffu, o.w, 8);
        o.x += __shfl_xor_sync(0xffffffffu, o.x, 16);
        o.y += __shfl_xor_sync(0xffffffffu, o.y, 16);
        o.z += __shfl_xor_sync(0xffffffffu, o.z, 16);
        o.w += __shfl_xor_sync(0xffffffffu, o.w, 16);
        if (lane < 8) {
            reinterpret_cast<float4*>(out)[n * 8 + lane] =
                make_float4(o.x * 0.25f, o.y * 0.25f, o.z * 0.25f, o.w * 0.25f);
        }
    } else {
        reinterpret_cast<float4*>(out)[n * 32 + lane] = o;
    }
}

// ---------------- launcher --------------------------------------------------
extern "C" void kernel_launch(void* const* d_in, const int* in_sizes, int n_in,
                              void* d_out, int out_size)
{
    const float* x   = (const float*)d_in[0];
    const int*   src = (const int*)d_in[1];
    const int*   dst = (const int*)d_in[2];
    const float* W0  = (const float*)d_in[3];
    const float* al0 = (const float*)d_in[4];
    const float* ar0 = (const float*)d_in[5];
    const float* W1  = (const float*)d_in[6];
    const float* al1 = (const float*)d_in[7];
    const float* ar1 = (const float*)d_in[8];
    const float* W2  = (const float*)d_in[9];
    const float* al2 = (const float*)d_in[10];
    const float* ar2 = (const float*)d_in[11];
    float* out = (float*)d_out;

    float *h1 = nullptr, *h2 = nullptr;
    cudaGetSymbolAddress((void**)&h1, g_h1);
    cudaGetSymbolAddress((void**)&h2, g_h2);

    const int smem_bytes = (F * F + F * HT_STRIDE) * sizeof(float);  // ~97KB
    static int smem_set = 0;
    if (!smem_set) {
        cudaFuncSetAttribute(gemm_attn_kernel,
                             cudaFuncAttributeMaxDynamicSharedMemorySize, smem_bytes);
        smem_set = 1;
    }

    const int gemm_grid = (NN + RPB - 1) / RPB;   // 782
    const int agg_grid  = (NN * 32) / 256;        // 6250 (exact)

    rowptr_kernel<<<(NN + 1 + 255) / 256, 256>>>(dst);

    // layer 0: no residual, ELU
    gemm_attn_kernel<<<gemm_grid, 256, smem_bytes>>>(x, W0, al0, ar0);
    gat_agg_kernel<<<agg_grid, 256>>>(src, nullptr, h1, /*act=*/1, /*mean=*/0);

    // layer 1: residual (input h1), ELU
    gemm_attn_kernel<<<gemm_grid, 256, smem_bytes>>>(h1, W1, al1, ar1);
    gat_agg_kernel<<<agg_grid, 256>>>(src, h1, h2, /*act=*/1, /*mean=*/0);

    // layer 2: residual (input h2), no act, mean over heads -> [N, 32]
    gemm_attn_kernel<<<gemm_grid, 256, smem_bytes>>>(h2, W2, al2, ar2);
    gat_agg_kernel<<<agg_grid, 256>>>(src, h2, out, /*act=*/0, /*mean=*/1);
}